// round 1
// baseline (speedup 1.0000x reference)
#include <cuda_runtime.h>
#include <math.h>
#include <stdint.h>

// Problem constants (fixed shapes from setup_inputs)
#define BB 8
#define CC 5
#define HH 768
#define WW 768
#define HW (HH*WW)
#define NPIX (BB*HW)          // 4,718,592
#define NTC 4                 // num_target_classes

#define EPSF 1e-7f
// f32 value of (1.0 - 1e-7) as jnp computes it (python double -> f32)
#define ONEMF ((float)(1.0 - 1e-7))

// ---------------- static device scratch (no allocation allowed) ----------------
__device__ unsigned char g_pm[NPIX];          // argmax class per pixel (0..4)
__device__ int           g_label[NPIX];       // union-find labels
__device__ unsigned long long g_cnt[20];      // joint counts [tm 0..3][pm 0..4]
__device__ double        g_spho[20];          // sum pho
__device__ double        g_slog[20];          // sum log(clip(pho))
__device__ double        g_slog1p[20];        // sum log1p(-clip(pho))
__device__ int           g_ncomp[4];          // component counts per class 1..4

// ---------------- K0: zero accumulators ----------------
__global__ void k_zero() {
    int t = threadIdx.x;
    if (t < 20) { g_cnt[t] = 0ULL; g_spho[t] = 0.0; g_slog[t] = 0.0; g_slog1p[t] = 0.0; }
    if (t < 4)  { g_ncomp[t] = 0; }
}

// ---------------- K1: argmax + label init + joint stats ----------------
__global__ void k_argmax_stats(const float* __restrict__ pred,
                               const int*   __restrict__ tmask) {
    __shared__ float        s_pho[20], s_log[20], s_log1p[20];
    __shared__ unsigned int s_cnt[20];
    int tid = threadIdx.x;
    if (tid < 20) { s_pho[tid] = 0.f; s_log[tid] = 0.f; s_log1p[tid] = 0.f; s_cnt[tid] = 0u; }
    __syncthreads();

    int stride = gridDim.x * blockDim.x;
    for (int i = blockIdx.x * blockDim.x + threadIdx.x; i < NPIX; i += stride) {
        int b = i / HW;
        int p = i - b * HW;
        const float* base = pred + (size_t)b * CC * HW + p;
        // argmax over C, first-index wins on ties (strict >)
        float best = base[0];
        int bc = 0;
        #pragma unroll
        for (int c = 1; c < CC; c++) {
            float v = base[(size_t)c * HW];
            if (v > best) { best = v; bc = c; }
        }
        g_pm[i] = (unsigned char)bc;
        g_label[i] = i;

        float q = (bc == 0) ? 0.0f : best;    // pho
        int t = tmask[i];
        if (t < 0) t = 0; if (t > 3) t = 3;   // defensive clamp
        int cell = t * 5 + bc;
        float qc = fminf(fmaxf(q, EPSF), ONEMF);
        atomicAdd(&s_cnt[cell], 1u);
        atomicAdd(&s_pho[cell], q);
        atomicAdd(&s_log[cell], logf(qc));
        atomicAdd(&s_log1p[cell], log1pf(-qc));
    }
    __syncthreads();
    if (tid < 20) {
        atomicAdd(&g_cnt[tid], (unsigned long long)s_cnt[tid]);
        atomicAdd(&g_spho[tid], (double)s_pho[tid]);
        atomicAdd(&g_slog[tid], (double)s_log[tid]);
        atomicAdd(&g_slog1p[tid], (double)s_log1p[tid]);
    }
}

// ---------------- union-find (lock-free; links always point to smaller index) ----------------
__device__ __forceinline__ int uf_find(int x) {
    int r = x;
    int l = g_label[r];
    while (l != r) { r = l; l = g_label[r]; }
    // path compression (benign races: writes always point to an ancestor, indices strictly decrease)
    int c = x;
    while (c != r) {
        int n = g_label[c];
        g_label[c] = r;
        c = n;
        if (c == r) break;
        if (n == c) break;
    }
    return r;
}

__device__ __forceinline__ void uf_union(int a, int b) {
    while (true) {
        a = uf_find(a);
        b = uf_find(b);
        if (a == b) return;
        if (a < b) { int t = a; a = b; b = t; }   // a > b: link a -> b
        int old = atomicCAS(&g_label[a], a, b);
        if (old == a) return;
        a = old;  // fresh value from CAS; retry
    }
}

// ---------------- K2: merge 4-neighbors of same nonzero class ----------------
__global__ void k_merge() {
    int stride = gridDim.x * blockDim.x;
    for (int i = blockIdx.x * blockDim.x + threadIdx.x; i < NPIX; i += stride) {
        int c = g_pm[i];
        if (c == 0) continue;
        int p = i % HW;
        int w = p % WW;
        if (w != 0 && g_pm[i - 1] == c)  uf_union(i, i - 1);
        if (p >= WW && g_pm[i - WW] == c) uf_union(i, i - WW);
    }
}

// ---------------- K3: count roots per class ----------------
__global__ void k_count() {
    __shared__ int s[4];
    if (threadIdx.x < 4) s[threadIdx.x] = 0;
    __syncthreads();
    int loc[4] = {0, 0, 0, 0};
    int stride = gridDim.x * blockDim.x;
    for (int i = blockIdx.x * blockDim.x + threadIdx.x; i < NPIX; i += stride) {
        int c = g_pm[i];
        if (c != 0 && g_label[i] == i) loc[c - 1]++;
    }
    #pragma unroll
    for (int k = 0; k < 4; k++) if (loc[k]) atomicAdd(&s[k], loc[k]);
    __syncthreads();
    if (threadIdx.x < 4 && s[threadIdx.x]) atomicAdd(&g_ncomp[threadIdx.x], s[threadIdx.x]);
}

// ---------------- K4: scalar assembly (single thread) ----------------
__global__ void k_final(float* __restrict__ out) {
    if (threadIdx.x != 0 || blockIdx.x != 0) return;

    // load stats
    long long cnt[4][5];
    double spho[4][5], slog[4][5], slog1p[4][5];
    for (int t = 0; t < 4; t++)
        for (int c = 0; c < 5; c++) {
            int k = t * 5 + c;
            cnt[t][c] = (long long)g_cnt[k];
            spho[t][c] = g_spho[k];
            slog[t][c] = g_slog[k];
            slog1p[t][c] = g_slog1p[k];
        }
    long long cpm[5] = {0, 0, 0, 0, 0};   // pixels per pred class
    long long ctm[4] = {0, 0, 0, 0};      // pixels per target class
    for (int t = 0; t < 4; t++)
        for (int c = 0; c < 5; c++) { cpm[c] += cnt[t][c]; ctm[t] += cnt[t][c]; }

    // ---- exact-f32 emulation of ph class values ----
    float phv[5] = {0.f, 0.f, 0.f, 0.f, 0.f};
    int last_i = 1;
    for (int v = 1; v < 5; v++) {
        bool present = (cpm[v] > 0);
        int has_bg = (cpm[v] < (long long)NPIX) ? 1 : 0;
        int nc = g_ncomp[v - 1];
        // int32 wraparound multiply, then round-to-nearest cast to f32 (matches jnp)
        int wrapped = (int)((unsigned int)nc * (unsigned int)last_i);
        float s = (float)wrapped;
        if (present) {
            #pragma unroll
            for (int c = 0; c < 5; c++) {
                float ind = (c == v) ? 1.0f : 0.0f;
                float inc = ind + s;       // one rounding
                phv[c] = phv[c] + inc;     // one rounding
            }
            last_i += nc + has_bg;
        }
    }

    const double Nd = (double)NPIX;
    const double dEPS  = (double)EPSF;    // exact f32 eps value
    const double dONEM = (double)ONEMF;   // exact f32 (1-eps)
    const double LOG_EPS      = log(dEPS);
    const double LOG_ONEM     = log(dONEM);
    const double LOG1P_NEPS   = log1p(-dEPS);
    const double LOG1P_NONEM  = log1p(-dONEM);   // = log(1 - (1-eps_f32))

    double res = 0.0;

    // ---- term 0: bce_dice(pm==0, tm==0) ----
    {
        long long n00 = cnt[0][0];
        long long np0 = cpm[0];
        long long nt0 = ctm[0];
        double bsum = (double)n00 * LOG_ONEM
                    + (double)(nt0 - n00) * LOG_EPS
                    + (double)(np0 - n00) * LOG1P_NONEM
                    + (double)((long long)NPIX - nt0 - np0 + n00) * LOG1P_NEPS;
        double bce = -bsum / Nd;
        double dice = 1.0 - (2.0 * (double)n00 + 1.0) / ((double)np0 + (double)nt0 + 1.0);
        res += bce + dice;
    }

    // ---- terms t = 1..3 ----
    for (int t = 1; t < NTC; t++) {
        long long nt = ctm[t];
        if (nt <= 0) continue;   // present == false -> contributes 0

        // weighted median of phv over target-mask pixels
        int ord[5] = {0, 1, 2, 3, 4};
        for (int i = 1; i < 5; i++) {
            int o = ord[i]; float v = phv[o]; int j = i - 1;
            while (j >= 0 && phv[ord[j]] > v) { ord[j + 1] = ord[j]; j--; }
            ord[j + 1] = o;
        }
        long long kk = (nt - 1) / 2;
        float med = phv[ord[4]];
        long long cum = 0;
        for (int j = 0; j < 5; j++) {
            cum += cnt[t][ord[j]];
            if (cum > kk) { med = phv[ord[j]]; break; }
        }
        bool sel[5];
        #pragma unroll
        for (int c = 0; c < 5; c++) sel[c] = (phv[c] == med);  // exact f32 compare

        double bsum = 0.0, sum_p = 0.0, inter = 0.0, extra_sum = 0.0;
        for (int c = 0; c < 5; c++) {
            if (sel[c]) {
                bsum += slog[t][c];           // target pixels, p = pho
                inter += spho[t][c];
                for (int tt = 0; tt < 4; tt++) {
                    sum_p += spho[tt][c];
                    if (tt != t) bsum += slog1p[tt][c];   // non-target, p = pho
                }
            } else {
                bsum += (double)cnt[t][c] * LOG_EPS;          // target, p = 0 -> eps
                extra_sum += spho[t][c];
                for (int tt = 0; tt < 4; tt++)
                    if (tt != t) bsum += (double)cnt[tt][c] * LOG1P_NEPS;  // non-target, p = 0
            }
        }
        double bce = -bsum / Nd;
        double dice = 1.0 - (2.0 * inter + 1.0) / (sum_p + (double)nt + 1.0);
        double extra = extra_sum / (double)(nt > 0 ? nt : 1);
        res += bce + dice + extra;
    }

    int nu = 0;
    for (int t = 0; t < NTC; t++) if (ctm[t] > 0) nu++;
    out[0] = (float)(res / (double)(2 * nu + 1));
}

// ---------------- launch ----------------
extern "C" void kernel_launch(void* const* d_in, const int* in_sizes, int n_in,
                              void* d_out, int out_size) {
    const float* pred = (const float*)d_in[0];
    const int*   tm   = (const int*)d_in[1];
    float* out = (float*)d_out;
    (void)in_sizes; (void)n_in; (void)out_size;

    const int blocks = 1184;   // 148 SMs * 8
    const int tpb = 256;
    k_zero<<<1, 32>>>();
    k_argmax_stats<<<blocks, tpb>>>(pred, tm);
    k_merge<<<blocks, tpb>>>();
    k_count<<<blocks, tpb>>>();
    k_final<<<1, 1>>>(out);
}